// round 13
// baseline (speedup 1.0000x reference)
#include <cuda_runtime.h>
#include <cuda_bf16.h>

#define B_ 4
#define H_ 224
#define W_ 224
#define C_ 64
#define K_ 8
#define EPS_ 1e-6f

#define STX (W_ * C_)
#define STP (W_ * C_)       // plane row stride (224 cols x 64 ch)
#define RT_ 248             // padded rows per plane (pads stay zero forever)
#define CH_ 28              // rows per kB chunk (8 chunks -> ~3 waves)

// Row-shifted planes: at kB step i, all four inserts live at storage row s=i+16.
// plane2[s] = M2[s-15], plane4[s] = M4[s-14], plane8[s] = M8[s-12], plane16[s] = M16[s-8]
// where M2[t][j] = h2 row t cols [j,j+1]; M4: [j-1,j+2]; M8: [j-3,j+4]; M16: [j-7,j+8].
__device__ float g_M2[(size_t)B_ * RT_ * STP];
__device__ float g_M4[(size_t)B_ * RT_ * STP];
__device__ float g_M8[(size_t)B_ * RT_ * STP];
__device__ float g_M16[(size_t)B_ * RT_ * STP];
__device__ float g_rmn[B_ * H_], g_rmx[B_ * H_];

// One-pass streaming front-end: per-row min/max + all 4 horizontal widths.
__global__ void __launch_bounds__(256) kA(const float* __restrict__ x) {
    const int c = threadIdx.x;                  // 0..63
    const int seg = threadIdx.y;                // 0..3
    const int t = blockIdx.x;                   // image row
    const int b = blockIdx.y;

    const float* xr = x + (((size_t)b * H_ + t) * W_) * C_ + c;
    float* p2s  = g_M2  + ((size_t)b * RT_ + t + 15) * STP + c;
    float* p4s  = g_M4  + ((size_t)b * RT_ + t + 14) * STP + c;
    float* p8s  = g_M8  + ((size_t)b * RT_ + t + 12) * STP + c;
    float* p16s = g_M16 + ((size_t)b * RT_ + t +  8) * STP + c;

    const int u0  = seg * 64;
    const int len = (seg == 3) ? 40 : 64;       // scan u in [u0, u0+len), total 232

    float mn = 3.402823466e38f, mx = -3.402823466e38f;
    float ring[8], ring8[8];

    // warmup: h2 for u0-15..u0-1, ring h2 (last 7), ring8 h8 (last 8)
    float xprev;
    {
        float hw[15];
        int up = u0 - 16;
        float xp = (up >= 0 && up <= 223) ? xr[up * C_] : 0.f;
        #pragma unroll
        for (int d = -15; d <= -1; d++) {
            const int u = u0 + d;
            float xc = (u >= 0 && u <= 223) ? xr[u * C_] : 0.f;
            hw[d + 15] = xp + xc;
            xp = xc;
        }
        xprev = xp;
        #pragma unroll
        for (int d = -7; d <= -1; d++) ring[(u0 + d) & 7] = hw[d + 15];
        #pragma unroll
        for (int d = -8; d <= -1; d++)
            ring8[(u0 + d) & 7] = (hw[d + 15] + hw[d + 13]) + (hw[d + 11] + hw[d + 9]);
    }

    for (int base = 0; base < len; base += 8) {
        #pragma unroll
        for (int vv = 0; vv < 8; vv++) {
            const int u = u0 + base + vv;
            float xc = 0.f;
            if (u <= 223) {
                xc = xr[u * C_];
                mn = fminf(mn, xc);
                mx = fmaxf(mx, xc);
            }
            const float h2 = xprev + xc;
            xprev = xc;
            const float h4 = h2 + ring[(u - 2) & 7];
            const float h8 = h4 + (ring[(u - 4) & 7] + ring[(u - 6) & 7]);
            const float h16 = h8 + ring8[(u - 8) & 7];
            ring[u & 7]  = h2;
            ring8[u & 7] = h8;
            if (u >= 1 && u <= 224) p2s[(u - 1) * C_] = h2;
            if (u >= 2 && u <= 225) p4s[(u - 2) * C_] = h4;
            if (u >= 4 && u <= 227) p8s[(u - 4) * C_] = h8;
            if (u >= 8)             p16s[(u - 8) * C_] = h16;
        }
    }

    #pragma unroll
    for (int o = 16; o; o >>= 1) {
        mn = fminf(mn, __shfl_xor_sync(0xffffffffu, mn, o));
        mx = fmaxf(mx, __shfl_xor_sync(0xffffffffu, mx, o));
    }
    __shared__ float smn[8], smx[8];
    const int tid = threadIdx.y * 64 + threadIdx.x;
    if ((tid & 31) == 0) { smn[tid >> 5] = mn; smx[tid >> 5] = mx; }
    __syncthreads();
    if (tid == 0) {
        #pragma unroll
        for (int i = 1; i < 8; i++) { mn = fminf(mn, smn[i]); mx = fmaxf(mx, smx[i]); }
        g_rmn[b * H_ + t] = mn;
        g_rmx[b * H_ + t] = mx;
    }
}

struct TailC { float inv, c0, c1, c2, c3, bsc, bsh; };  // c0..c3 pre-scaled by ln2

static __device__ __forceinline__ float tail_sig(
    float m2, float m4, float m8, float m16, float4 tb,
    const TailC& tc, const float4* s_aw4, int c)
{
    const float ly0 = __log2f(fmaf(m2,  tc.inv, tb.x));
    const float ly1 = __log2f(fmaf(m4,  tc.inv, tb.y));
    const float ly2 = __log2f(fmaf(m8,  tc.inv, tb.z));
    const float ly3 = __log2f(fmaf(m16, tc.inv, tb.w));
    const float alpha = fmaf(tc.c3, ly3, fmaf(tc.c2, ly2, fmaf(tc.c1, ly1, tc.c0 * ly0)));
    const float a = fmaf(alpha, tc.bsc, tc.bsh);
    float cnt = 0.f;
    #pragma unroll
    for (int k2 = 0; k2 < 4; k2++) {
        const float4 aw = s_aw4[k2 * C_ + c];
        cnt += fmaxf(fmaf(-aw.y, fabsf(a - aw.x), 1.f), 0.f);
        cnt += fmaxf(fmaf(-aw.w, fabsf(a - aw.z), 1.f), 0.f);
    }
    float e, r;
    asm("ex2.approx.ftz.f32 %0, %1;" : "=f"(e) : "f"(cnt * -1.44269504f));
    asm("rcp.approx.ftz.f32 %0, %1;" : "=f"(r) : "f"(1.f + e));
    return r;
}

__global__ void __launch_bounds__(64, 16) kB(
    const float* __restrict__ x,    const float* __restrict__ olsw,
    const float* __restrict__ anch, const float* __restrict__ wdth,
    const float* __restrict__ gmm,  const float* __restrict__ bta,
    const float* __restrict__ mea,  const float* __restrict__ vrr,
    float* __restrict__ out)
{
    const int c = threadIdx.x;
    const int j = blockIdx.x;
    const int i0 = blockIdx.y * CH_;
    const int b = blockIdx.z;

    float mn = 3.402823466e38f, mx = -3.402823466e38f;
    for (int i = c; i < H_; i += 64) {
        mn = fminf(mn, g_rmn[b * H_ + i]);
        mx = fmaxf(mx, g_rmx[b * H_ + i]);
    }
    #pragma unroll
    for (int o = 16; o; o >>= 1) {
        mn = fminf(mn, __shfl_xor_sync(0xffffffffu, mn, o));
        mx = fmaxf(mx, __shfl_xor_sync(0xffffffffu, mx, o));
    }
    __shared__ float sred[4];
    if ((c & 31) == 0) { sred[(c >> 5)] = mn; sred[(c >> 5) + 2] = mx; }
    __syncthreads();
    mn = fminf(sred[0], sred[1]);
    mx = fmaxf(sred[2], sred[3]);

    const float w0 = olsw[0], w1 = olsw[1], w2 = olsw[2], w3 = olsw[3];
    const float L1 = 0.69314718f, L2 = 1.38629436f, L3 = 2.07944154f, L4 = 2.77258872f;
    const float wsum = w0 + w1 + w2 + w3;
    const float lrb = (w0 * L1 + w1 * L2 + w2 * L3 + w3 * L4) / wsum;
    const float d0 = L1 - lrb, d1 = L2 - lrb, d2 = L3 - lrb, d3 = L4 - lrb;
    const float den = w0 * d0 * d0 + w1 * d1 * d1 + w2 * d2 * d2 + w3 * d3 * d3;
    const float ivd = (1.f / den) * 0.69314718056f;   // fold ln2 (log2 -> ln)

    TailC tc;
    tc.inv = 1.f / (mx - mn + EPS_);
    tc.c0 = w0 * d0 * ivd; tc.c1 = w1 * d1 * ivd;
    tc.c2 = w2 * d2 * ivd; tc.c3 = w3 * d3 * ivd;
    tc.bsc = gmm[c] * rsqrtf(vrr[c] + 1e-3f);
    tc.bsh = bta[c] - mea[c] * tc.bsc;

    __shared__ float4 s_aw4[4 * C_];
    #pragma unroll
    for (int k2 = 0; k2 < 4; k2++)
        s_aw4[k2 * C_ + c] = make_float4(anch[c * K_ + 2 * k2],     wdth[c * K_ + 2 * k2],
                                         anch[c * K_ + 2 * k2 + 1], wdth[c * K_ + 2 * k2 + 1]);

    const float mi  = mn * tc.inv;
    const float nc2  = (float)(min(j + 1, 223) - j + 1);
    const float nc4  = (float)(min(j + 2, 223) - max(j - 1, 0) + 1);
    const float nc8  = (float)(min(j + 4, 223) - max(j - 3, 0) + 1);
    const float nc16 = (float)(min(j + 8, 223) - max(j - 7, 0) + 1);

    __shared__ float4 s_tab[H_];
    for (int i = c; i < H_; i += 64) {
        float nr2  = (float)(min(i + 1, 223) - i + 1);
        float nr4  = (float)(min(i + 2, 223) - max(i - 1, 0) + 1);
        float nr8  = (float)(min(i + 4, 223) - max(i - 3, 0) + 1);
        float nr16 = (float)(min(i + 8, 223) - max(i - 7, 0) + 1);
        s_tab[i] = make_float4(EPS_ - nr2 * nc2 * mi,  EPS_ - nr4 * nc4 * mi,
                               EPS_ - nr8 * nc8 * mi,  EPS_ - nr16 * nc16 * mi);
    }
    __syncthreads();

    // Plane bases at storage row i0; loads use compile-time row offsets.
    const size_t pb = ((size_t)b * RT_ + i0) * STP + j * C_ + c;
    const float* bp2  = g_M2  + pb;
    const float* bp4  = g_M4  + pb;
    const float* bp8  = g_M8  + pb;
    const float* bp16 = g_M16 + pb;
    const float* xr  = x   + ((size_t)b * H_ * W_ + j) * C_ + c + (size_t)i0 * STX;
    float*       orr = out + ((size_t)b * H_ * W_ + j) * C_ + c + (size_t)i0 * STX;

    float r2[2], r4[4], r8[8], r16[16];

    // prefill: rho = 1..15 covers rows i0-7..i0+7 (r16), i0-3..i0+3 (r8), etc.
    #pragma unroll
    for (int rho = 1; rho <= 15; rho++) {
        r16[(rho - 1) & 15] = bp16[rho * STP];
        if (rho >= 9)  r8[(rho - 9) & 7]  = bp8[rho * STP];
        if (rho >= 13) r4[(rho - 13) & 3] = bp4[rho * STP];
        if (rho == 15) r2[0]              = bp2[rho * STP];
    }

    #pragma unroll
    for (int base = 0; base < CH_; base += 16) {
        #pragma unroll
        for (int p = 0; p < 8; p++) {
            const int u = 2 * p;
            if (base + u >= CH_) break;
            const int rel = base + u;            // compile-time

            // first new rows: all four at storage row rel+16
            r16[(u + 15) & 15] = bp16[(rel + 16) * STP];
            r8 [(u + 7) & 7]   = bp8 [(rel + 16) * STP];
            r4 [(u + 3) & 3]   = bp4 [(rel + 16) * STP];
            r2 [(u + 1) & 1]   = bp2 [(rel + 16) * STP];

            #define Z16(s) (((s) == (u & 15)) ? 0.f : r16[s])
            const float A16 =
                ((((Z16(0)+Z16(1))+(Z16(2)+Z16(3)))+((Z16(4)+Z16(5))+(Z16(6)+Z16(7))))
               + (((Z16(8)+Z16(9))+(Z16(10)+Z16(11)))+((Z16(12)+Z16(13))+(Z16(14)+Z16(15)))));
            #undef Z16
            #define Z8(s) (((s) == (u & 7)) ? 0.f : r8[s])
            const float A8 = ((Z8(0)+Z8(1))+(Z8(2)+Z8(3)))+((Z8(4)+Z8(5))+(Z8(6)+Z8(7)));
            #undef Z8
            #define Z4(s) (((s) == (u & 3)) ? 0.f : r4[s])
            const float A4 = (Z4(0)+Z4(1))+(Z4(2)+Z4(3));
            #undef Z4

            const float m16_0 = A16 + r16[u & 15];
            const float m8_0  = A8  + r8[u & 7];
            const float m4_0  = A4  + r4[u & 3];
            const float m2_0  = r2[0] + r2[1];

            // second new rows: all four at storage row rel+17
            r16[u & 15] = bp16[(rel + 17) * STP];
            r8 [u & 7]  = bp8 [(rel + 17) * STP];
            r4 [u & 3]  = bp4 [(rel + 17) * STP];
            r2 [u & 1]  = bp2 [(rel + 17) * STP];

            const float m16_1 = A16 + r16[u & 15];
            const float m8_1  = A8  + r8[u & 7];
            const float m4_1  = A4  + r4[u & 3];
            const float m2_1  = r2[(u + 1) & 1] + r2[u & 1];

            const float sig0 = tail_sig(m2_0, m4_0, m8_0, m16_0, s_tab[i0 + rel],     tc, s_aw4, c);
            const float sig1 = tail_sig(m2_1, m4_1, m8_1, m16_1, s_tab[i0 + rel + 1], tc, s_aw4, c);
            orr[rel * STX]       = xr[rel * STX]       + sig0;
            orr[(rel + 1) * STX] = xr[(rel + 1) * STX] + sig1;
        }
    }
}

extern "C" void kernel_launch(void* const* d_in, const int* in_sizes, int n_in,
                              void* d_out, int out_size) {
    const float* x    = (const float*)d_in[0];
    const float* olsw = (const float*)d_in[1];
    const float* anch = (const float*)d_in[2];
    const float* wdth = (const float*)d_in[3];
    const float* gmm  = (const float*)d_in[4];
    const float* bta  = (const float*)d_in[5];
    const float* mea  = (const float*)d_in[6];
    const float* vrr  = (const float*)d_in[7];
    float* out = (float*)d_out;

    kA<<<dim3(H_, B_), dim3(C_, 4)>>>(x);
    kB<<<dim3(W_, H_ / CH_, B_), C_>>>(x, olsw, anch, wdth, gmm, bta, mea, vrr, out);
}

// round 14
// speedup vs baseline: 1.7093x; 1.7093x over previous
#include <cuda_runtime.h>
#include <cuda_bf16.h>

#define B_ 4
#define H_ 224
#define W_ 224
#define C_ 64
#define K_ 8
#define EPS_ 1e-6f

#define H2_W 226
#define H8_W 232
#define ST2 (H2_W * C_)
#define ST8 (H8_W * C_)
#define STX (W_ * C_)
#define RT_ 242             // 8 pad + 224 + 10 pad rows (pads stay zero forever)
#define CH_ 28              // rows per kB chunk (8 chunks -> ~3 waves)

__device__ float g_H2[(size_t)B_ * RT_ * ST2];
__device__ float g_H8[(size_t)B_ * RT_ * ST8];
__device__ float g_rmn[B_ * H_], g_rmx[B_ * H_];

// One-pass streaming front-end: per-row min/max + H2 + H8 (RAW sums).
// Writes real rows at +8 offset; pad rows are never touched (stay zero).
__global__ void __launch_bounds__(256) kA(const float* __restrict__ x) {
    const int c = threadIdx.x;
    const int seg = threadIdx.y;
    const int t = blockIdx.x;
    const int b = blockIdx.y;

    const float* xr  = x    + (((size_t)b * H_ + t) * W_) * C_ + c;
    float*       h2g = g_H2 + ((size_t)b * RT_ + 8 + t) * ST2 + c;
    float*       h8g = g_H8 + ((size_t)b * RT_ + 8 + t) * ST8 + c;

    const int u0  = seg * 64;
    const int len = (seg == 3) ? (H8_W - 192) : 64;

    float mn = 3.402823466e38f, mx = -3.402823466e38f;
    float ring[8];
    #pragma unroll
    for (int i = 0; i < 8; i++) ring[i] = 0.f;

    float xprev;
    {
        int up = u0 - 8;
        float xp = (up >= 0 && up <= 223) ? xr[up * C_] : 0.f;
        #pragma unroll
        for (int d = -7; d <= -1; d++) {
            const int u = u0 + d;
            float xc = (u >= 0 && u <= 223) ? xr[u * C_] : 0.f;
            ring[(d + 8) & 7] = xp + xc;
            xp = xc;
        }
        xprev = xp;
    }

    for (int base = 0; base < len; base += 8) {
        #pragma unroll
        for (int vv = 0; vv < 8; vv++) {
            const int v = base + vv;
            const int u = u0 + v;
            float xc = 0.f;
            if (u <= 223) {
                xc = xr[u * C_];
                mn = fminf(mn, xc);
                mx = fmaxf(mx, xc);
            }
            const float h2 = xprev + xc;
            xprev = xc;
            ring[v & 7] = h2;
            const float h8 = (h2 + ring[(v - 2) & 7])
                           + (ring[(v - 4) & 7] + ring[(v - 6) & 7]);
            if (u <= 225) h2g[u * C_] = h2;
            h8g[u * C_] = h8;
        }
    }

    #pragma unroll
    for (int o = 16; o; o >>= 1) {
        mn = fminf(mn, __shfl_xor_sync(0xffffffffu, mn, o));
        mx = fmaxf(mx, __shfl_xor_sync(0xffffffffu, mx, o));
    }
    __shared__ float smn[8], smx[8];
    const int tid = threadIdx.y * 64 + threadIdx.x;
    if ((tid & 31) == 0) { smn[tid >> 5] = mn; smx[tid >> 5] = mx; }
    __syncthreads();
    if (tid == 0) {
        #pragma unroll
        for (int i = 1; i < 8; i++) { mn = fminf(mn, smn[i]); mx = fmaxf(mx, smx[i]); }
        g_rmn[b * H_ + t] = mn;
        g_rmx[b * H_ + t] = mx;
    }
}

struct TailC { float inv, c0, c1, c2, c3, bsc, bsh; };  // c0..c3 pre-scaled by ln2

static __device__ __forceinline__ float tail_sig(
    float m2, float m4, float m8, float m16, float4 tb,
    const TailC& tc, const float4* s_aw4, int c)
{
    const float ly0 = __log2f(fmaf(m2,  tc.inv, tb.x));
    const float ly1 = __log2f(fmaf(m4,  tc.inv, tb.y));
    const float ly2 = __log2f(fmaf(m8,  tc.inv, tb.z));
    const float ly3 = __log2f(fmaf(m16, tc.inv, tb.w));
    const float alpha = fmaf(tc.c3, ly3, fmaf(tc.c2, ly2, fmaf(tc.c1, ly1, tc.c0 * ly0)));
    const float a = fmaf(alpha, tc.bsc, tc.bsh);
    float cnt = 0.f;
    #pragma unroll
    for (int k2 = 0; k2 < 4; k2++) {
        const float4 aw = s_aw4[k2 * C_ + c];
        cnt += fmaxf(fmaf(-aw.y, fabsf(a - aw.x), 1.f), 0.f);
        cnt += fmaxf(fmaf(-aw.w, fabsf(a - aw.z), 1.f), 0.f);
    }
    float e, r;
    asm("ex2.approx.ftz.f32 %0, %1;" : "=f"(e) : "f"(cnt * -1.44269504f));
    asm("rcp.approx.ftz.f32 %0, %1;" : "=f"(r) : "f"(1.f + e));
    return r;
}

__global__ void __launch_bounds__(64, 16) kB(
    const float* __restrict__ x,    const float* __restrict__ olsw,
    const float* __restrict__ anch, const float* __restrict__ wdth,
    const float* __restrict__ gmm,  const float* __restrict__ bta,
    const float* __restrict__ mea,  const float* __restrict__ vrr,
    float* __restrict__ out)
{
    const int c = threadIdx.x;
    const int j = blockIdx.x;
    const int i0 = blockIdx.y * CH_;
    const int b = blockIdx.z;

    float mn = 3.402823466e38f, mx = -3.402823466e38f;
    for (int i = c; i < H_; i += 64) {
        mn = fminf(mn, g_rmn[b * H_ + i]);
        mx = fmaxf(mx, g_rmx[b * H_ + i]);
    }
    #pragma unroll
    for (int o = 16; o; o >>= 1) {
        mn = fminf(mn, __shfl_xor_sync(0xffffffffu, mn, o));
        mx = fmaxf(mx, __shfl_xor_sync(0xffffffffu, mx, o));
    }
    __shared__ float sred[4];
    if ((c & 31) == 0) { sred[(c >> 5)] = mn; sred[(c >> 5) + 2] = mx; }
    __syncthreads();
    mn = fminf(sred[0], sred[1]);
    mx = fmaxf(sred[2], sred[3]);

    const float w0 = olsw[0], w1 = olsw[1], w2 = olsw[2], w3 = olsw[3];
    const float L1 = 0.69314718f, L2 = 1.38629436f, L3 = 2.07944154f, L4 = 2.77258872f;
    const float wsum = w0 + w1 + w2 + w3;
    const float lrb = (w0 * L1 + w1 * L2 + w2 * L3 + w3 * L4) / wsum;
    const float d0 = L1 - lrb, d1 = L2 - lrb, d2 = L3 - lrb, d3 = L4 - lrb;
    const float den = w0 * d0 * d0 + w1 * d1 * d1 + w2 * d2 * d2 + w3 * d3 * d3;
    const float ivd = (1.f / den) * 0.69314718056f;   // fold ln2 (log2 -> ln)

    TailC tc;
    tc.inv = 1.f / (mx - mn + EPS_);
    tc.c0 = w0 * d0 * ivd; tc.c1 = w1 * d1 * ivd;
    tc.c2 = w2 * d2 * ivd; tc.c3 = w3 * d3 * ivd;
    tc.bsc = gmm[c] * rsqrtf(vrr[c] + 1e-3f);
    tc.bsh = bta[c] - mea[c] * tc.bsc;

    __shared__ float4 s_aw4[4 * C_];
    #pragma unroll
    for (int k2 = 0; k2 < 4; k2++)
        s_aw4[k2 * C_ + c] = make_float4(anch[c * K_ + 2 * k2],     wdth[c * K_ + 2 * k2],
                                         anch[c * K_ + 2 * k2 + 1], wdth[c * K_ + 2 * k2 + 1]);

    const float mi  = mn * tc.inv;
    const float nc2  = (float)(min(j + 1, 223) - j + 1);
    const float nc4  = (float)(min(j + 2, 223) - max(j - 1, 0) + 1);
    const float nc8  = (float)(min(j + 4, 223) - max(j - 3, 0) + 1);
    const float nc16 = (float)(min(j + 8, 223) - max(j - 7, 0) + 1);

    __shared__ float4 s_tab[H_];
    for (int i = c; i < H_; i += 64) {
        float nr2  = (float)(min(i + 1, 223) - i + 1);
        float nr4  = (float)(min(i + 2, 223) - max(i - 1, 0) + 1);
        float nr8  = (float)(min(i + 4, 223) - max(i - 3, 0) + 1);
        float nr16 = (float)(min(i + 8, 223) - max(i - 7, 0) + 1);
        s_tab[i] = make_float4(EPS_ - nr2 * nc2 * mi,  EPS_ - nr4 * nc4 * mi,
                               EPS_ - nr8 * nc8 * mi,  EPS_ - nr16 * nc16 * mi);
    }
    __syncthreads();

    // Base pointers at relative row 0 == actual row (i0 - 7), i.e. padded row (i0 + 1).
    const float* bH8 = g_H8 + (size_t)b * RT_ * ST8 + (size_t)(i0 + 1) * ST8 + j * C_ + c;
    const float* bH2 = g_H2 + (size_t)b * RT_ * ST2 + (size_t)(i0 + 1) * ST2 + j * C_ + c;
    const float* xr  = x   + ((size_t)b * H_ * W_ + j) * C_ + c + (size_t)i0 * STX;
    float*       orr = out + ((size_t)b * H_ * W_ + j) * C_ + c + (size_t)i0 * STX;

    float r2[2], r4[4], r8[8], r16[16];

    // prefill rel rows 0..14 (== actual i0-7 .. i0+7); pads are zero
    #pragma unroll
    for (int d = -7; d <= 7; d++) {
        const int rr = d + 7;
        r16[rr & 15] = bH8[rr * ST8] + bH8[rr * ST8 + 8 * C_];
        if (d >= -3 && d <= 3) r8[d + 3] = bH8[rr * ST8 + 4 * C_];
        if (d >= -1 && d <= 1) r4[d + 1] = bH2[rr * ST2] + bH2[rr * ST2 + 2 * C_];
        if (d == 0)            r2[0]     = bH2[rr * ST2 + C_];
    }

    #pragma unroll
    for (int base = 0; base < CH_; base += 16) {
        #pragma unroll
        for (int p = 0; p < 8; p++) {
            const int u = 2 * p;
            if (base + u >= CH_) break;
            const int rel = base + u;            // compile-time

            // ---- insert first new rows (i+8 / i+4 / i+2 / i+1) ----
            r16[(u + 15) & 15] = bH8[(rel + 15) * ST8] + bH8[(rel + 15) * ST8 + 8 * C_];
            r8 [(u + 7) & 7]   = bH8[(rel + 11) * ST8 + 4 * C_];
            r4 [(u + 3) & 3]   = bH2[(rel + 9) * ST2] + bH2[(rel + 9) * ST2 + 2 * C_];
            r2 [(u + 1) & 1]   = bH2[(rel + 8) * ST2 + C_];

            // ---- shared cores (excluded slot folded as +0.f) ----
            #define Z16(s) (((s) == (u & 15)) ? 0.f : r16[s])
            const float A16 =
                ((((Z16(0)+Z16(1))+(Z16(2)+Z16(3)))+((Z16(4)+Z16(5))+(Z16(6)+Z16(7))))
               + (((Z16(8)+Z16(9))+(Z16(10)+Z16(11)))+((Z16(12)+Z16(13))+(Z16(14)+Z16(15)))));
            #undef Z16
            #define Z8(s) (((s) == (u & 7)) ? 0.f : r8[s])
            const float A8 = ((Z8(0)+Z8(1))+(Z8(2)+Z8(3)))+((Z8(4)+Z8(5))+(Z8(6)+Z8(7)));
            #undef Z8
            #define Z4(s) (((s) == (u & 3)) ? 0.f : r4[s])
            const float A4 = (Z4(0)+Z4(1))+(Z4(2)+Z4(3));
            #undef Z4

            const float m16_0 = A16 + r16[u & 15];
            const float m8_0  = A8  + r8[u & 7];
            const float m4_0  = A4  + r4[u & 3];
            const float m2_0  = r2[0] + r2[1];

            // ---- insert second new rows (i+9 / i+5 / i+3 / i+2) into freed slots ----
            r16[u & 15] = bH8[(rel + 16) * ST8] + bH8[(rel + 16) * ST8 + 8 * C_];
            r8 [u & 7]  = bH8[(rel + 12) * ST8 + 4 * C_];
            r4 [u & 3]  = bH2[(rel + 10) * ST2] + bH2[(rel + 10) * ST2 + 2 * C_];
            r2 [u & 1]  = bH2[(rel + 9) * ST2 + C_];

            const float m16_1 = A16 + r16[u & 15];
            const float m8_1  = A8  + r8[u & 7];
            const float m4_1  = A4  + r4[u & 3];
            const float m2_1  = r2[(u + 1) & 1] + r2[u & 1];

            const float sig0 = tail_sig(m2_0, m4_0, m8_0, m16_0, s_tab[i0 + rel],     tc, s_aw4, c);
            const float sig1 = tail_sig(m2_1, m4_1, m8_1, m16_1, s_tab[i0 + rel + 1], tc, s_aw4, c);
            orr[rel * STX]       = xr[rel * STX]       + sig0;
            orr[(rel + 1) * STX] = xr[(rel + 1) * STX] + sig1;
        }
    }
}

extern "C" void kernel_launch(void* const* d_in, const int* in_sizes, int n_in,
                              void* d_out, int out_size) {
    const float* x    = (const float*)d_in[0];
    const float* olsw = (const float*)d_in[1];
    const float* anch = (const float*)d_in[2];
    const float* wdth = (const float*)d_in[3];
    const float* gmm  = (const float*)d_in[4];
    const float* bta  = (const float*)d_in[5];
    const float* mea  = (const float*)d_in[6];
    const float* vrr  = (const float*)d_in[7];
    float* out = (float*)d_out;

    kA<<<dim3(H_, B_), dim3(C_, 4)>>>(x);
    kB<<<dim3(W_, H_ / CH_, B_), C_>>>(x, olsw, anch, wdth, gmm, bta, mea, vrr, out);
}

// round 15
// speedup vs baseline: 2.1616x; 1.2646x over previous
#include <cuda_runtime.h>
#include <cuda_bf16.h>

#define B_ 4
#define H_ 224
#define W_ 224
#define C_ 64
#define K_ 8
#define EPS_ 1e-6f

#define H2_W 226
#define H8_W 232
#define ST2 (H2_W * C_)
#define ST8 (H8_W * C_)
#define STX (W_ * C_)
#define RT_ 242             // 8 pad + 224 + 10 pad rows (pads stay zero forever)
#define CH_ 28              // rows per kB chunk (8 chunks)

__device__ float g_H2[(size_t)B_ * RT_ * ST2];
__device__ float g_H8[(size_t)B_ * RT_ * ST8];
__device__ float g_rmn[B_ * H_], g_rmx[B_ * H_];

// One-pass streaming front-end: per-row min/max + H2 + H8 (RAW sums).
__global__ void __launch_bounds__(256) kA(const float* __restrict__ x) {
    const int c = threadIdx.x;
    const int seg = threadIdx.y;
    const int t = blockIdx.x;
    const int b = blockIdx.y;

    const float* xr  = x    + (((size_t)b * H_ + t) * W_) * C_ + c;
    float*       h2g = g_H2 + ((size_t)b * RT_ + 8 + t) * ST2 + c;
    float*       h8g = g_H8 + ((size_t)b * RT_ + 8 + t) * ST8 + c;

    const int u0  = seg * 64;
    const int len = (seg == 3) ? (H8_W - 192) : 64;

    float mn = 3.402823466e38f, mx = -3.402823466e38f;
    float ring[8];
    #pragma unroll
    for (int i = 0; i < 8; i++) ring[i] = 0.f;

    float xprev;
    {
        int up = u0 - 8;
        float xp = (up >= 0 && up <= 223) ? xr[up * C_] : 0.f;
        #pragma unroll
        for (int d = -7; d <= -1; d++) {
            const int u = u0 + d;
            float xc = (u >= 0 && u <= 223) ? xr[u * C_] : 0.f;
            ring[(d + 8) & 7] = xp + xc;
            xp = xc;
        }
        xprev = xp;
    }

    for (int base = 0; base < len; base += 8) {
        #pragma unroll
        for (int vv = 0; vv < 8; vv++) {
            const int v = base + vv;
            const int u = u0 + v;
            float xc = 0.f;
            if (u <= 223) {
                xc = xr[u * C_];
                mn = fminf(mn, xc);
                mx = fmaxf(mx, xc);
            }
            const float h2 = xprev + xc;
            xprev = xc;
            ring[v & 7] = h2;
            const float h8 = (h2 + ring[(v - 2) & 7])
                           + (ring[(v - 4) & 7] + ring[(v - 6) & 7]);
            if (u <= 225) h2g[u * C_] = h2;
            h8g[u * C_] = h8;
        }
    }

    #pragma unroll
    for (int o = 16; o; o >>= 1) {
        mn = fminf(mn, __shfl_xor_sync(0xffffffffu, mn, o));
        mx = fmaxf(mx, __shfl_xor_sync(0xffffffffu, mx, o));
    }
    __shared__ float smn[8], smx[8];
    const int tid = threadIdx.y * 64 + threadIdx.x;
    if ((tid & 31) == 0) { smn[tid >> 5] = mn; smx[tid >> 5] = mx; }
    __syncthreads();
    if (tid == 0) {
        #pragma unroll
        for (int i = 1; i < 8; i++) { mn = fminf(mn, smn[i]); mx = fmaxf(mx, smx[i]); }
        g_rmn[b * H_ + t] = mn;
        g_rmx[b * H_ + t] = mx;
    }
}

struct TailC { float inv, c0, c1, c2, c3, bsc, bsh; };  // c0..c3 pre-scaled by ln2

static __device__ __forceinline__ float tail_sig(
    float m2, float m4, float m8, float m16, float4 tb,
    const TailC& tc, const float4* s_aw4, int c)
{
    const float ly0 = __log2f(fmaf(m2,  tc.inv, tb.x));
    const float ly1 = __log2f(fmaf(m4,  tc.inv, tb.y));
    const float ly2 = __log2f(fmaf(m8,  tc.inv, tb.z));
    const float ly3 = __log2f(fmaf(m16, tc.inv, tb.w));
    const float alpha = fmaf(tc.c3, ly3, fmaf(tc.c2, ly2, fmaf(tc.c1, ly1, tc.c0 * ly0)));
    const float a = fmaf(alpha, tc.bsc, tc.bsh);
    float cnt = 0.f;
    #pragma unroll
    for (int k2 = 0; k2 < 4; k2++) {
        const float4 aw = s_aw4[k2 * C_ + c];
        cnt += fmaxf(fmaf(-aw.y, fabsf(a - aw.x), 1.f), 0.f);
        cnt += fmaxf(fmaf(-aw.w, fabsf(a - aw.z), 1.f), 0.f);
    }
    float e, r;
    asm("ex2.approx.ftz.f32 %0, %1;" : "=f"(e) : "f"(cnt * -1.44269504f));
    asm("rcp.approx.ftz.f32 %0, %1;" : "=f"(r) : "f"(1.f + e));
    return r;
}

__global__ void __launch_bounds__(64, 12) kB(
    const float* __restrict__ x,    const float* __restrict__ olsw,
    const float* __restrict__ anch, const float* __restrict__ wdth,
    const float* __restrict__ gmm,  const float* __restrict__ bta,
    const float* __restrict__ mea,  const float* __restrict__ vrr,
    float* __restrict__ out)
{
    const int c = threadIdx.x;
    const int j = blockIdx.x;
    const int i0 = blockIdx.y * CH_;
    const int b = blockIdx.z;

    float mn = 3.402823466e38f, mx = -3.402823466e38f;
    for (int i = c; i < H_; i += 64) {
        mn = fminf(mn, g_rmn[b * H_ + i]);
        mx = fmaxf(mx, g_rmx[b * H_ + i]);
    }
    #pragma unroll
    for (int o = 16; o; o >>= 1) {
        mn = fminf(mn, __shfl_xor_sync(0xffffffffu, mn, o));
        mx = fmaxf(mx, __shfl_xor_sync(0xffffffffu, mx, o));
    }
    __shared__ float sred[4];
    if ((c & 31) == 0) { sred[(c >> 5)] = mn; sred[(c >> 5) + 2] = mx; }
    __syncthreads();
    mn = fminf(sred[0], sred[1]);
    mx = fmaxf(sred[2], sred[3]);

    const float w0 = olsw[0], w1 = olsw[1], w2 = olsw[2], w3 = olsw[3];
    const float L1 = 0.69314718f, L2 = 1.38629436f, L3 = 2.07944154f, L4 = 2.77258872f;
    const float wsum = w0 + w1 + w2 + w3;
    const float lrb = (w0 * L1 + w1 * L2 + w2 * L3 + w3 * L4) / wsum;
    const float d0 = L1 - lrb, d1 = L2 - lrb, d2 = L3 - lrb, d3 = L4 - lrb;
    const float den = w0 * d0 * d0 + w1 * d1 * d1 + w2 * d2 * d2 + w3 * d3 * d3;
    const float ivd = (1.f / den) * 0.69314718056f;   // fold ln2 (log2 -> ln)

    TailC tc;
    tc.inv = 1.f / (mx - mn + EPS_);
    tc.c0 = w0 * d0 * ivd; tc.c1 = w1 * d1 * ivd;
    tc.c2 = w2 * d2 * ivd; tc.c3 = w3 * d3 * ivd;
    tc.bsc = gmm[c] * rsqrtf(vrr[c] + 1e-3f);
    tc.bsh = bta[c] - mea[c] * tc.bsc;

    __shared__ float4 s_aw4[4 * C_];
    #pragma unroll
    for (int k2 = 0; k2 < 4; k2++)
        s_aw4[k2 * C_ + c] = make_float4(anch[c * K_ + 2 * k2],     wdth[c * K_ + 2 * k2],
                                         anch[c * K_ + 2 * k2 + 1], wdth[c * K_ + 2 * k2 + 1]);

    const float mi  = mn * tc.inv;
    const float nc2  = (float)(min(j + 1, 223) - j + 1);
    const float nc4  = (float)(min(j + 2, 223) - max(j - 1, 0) + 1);
    const float nc8  = (float)(min(j + 4, 223) - max(j - 3, 0) + 1);
    const float nc16 = (float)(min(j + 8, 223) - max(j - 7, 0) + 1);

    __shared__ float4 s_tab[H_];
    for (int i = c; i < H_; i += 64) {
        float nr2  = (float)(min(i + 1, 223) - i + 1);
        float nr4  = (float)(min(i + 2, 223) - max(i - 1, 0) + 1);
        float nr8  = (float)(min(i + 4, 223) - max(i - 3, 0) + 1);
        float nr16 = (float)(min(i + 8, 223) - max(i - 7, 0) + 1);
        s_tab[i] = make_float4(EPS_ - nr2 * nc2 * mi,  EPS_ - nr4 * nc4 * mi,
                               EPS_ - nr8 * nc8 * mi,  EPS_ - nr16 * nc16 * mi);
    }
    __syncthreads();

    // Base pointers at relative row 0 == padded row (i0 + 1).
    const float* bH8 = g_H8 + (size_t)b * RT_ * ST8 + (size_t)(i0 + 1) * ST8 + j * C_ + c;
    const float* bH2 = g_H2 + (size_t)b * RT_ * ST2 + (size_t)(i0 + 1) * ST2 + j * C_ + c;
    const float* xr  = x   + ((size_t)b * H_ * W_ + j) * C_ + c + (size_t)i0 * STX;
    float*       orr = out + ((size_t)b * H_ * W_ + j) * C_ + c + (size_t)i0 * STX;

    float r2[2], r4[4], r8[8], r16[16];

    // prefill rel rows 0..14 (== actual i0-7 .. i0+7); pads are zero
    #pragma unroll
    for (int d = -7; d <= 7; d++) {
        const int rr = d + 7;
        r16[rr & 15] = bH8[rr * ST8] + bH8[rr * ST8 + 8 * C_];
        if (d >= -3 && d <= 3) r8[d + 3] = bH8[rr * ST8 + 4 * C_];
        if (d >= -1 && d <= 1) r4[d + 1] = bH2[rr * ST2] + bH2[rr * ST2 + 2 * C_];
        if (d == 0)            r2[0]     = bH2[rr * ST2 + C_];
    }

    // prefetch registers for the NEXT iteration's 12 loads
    float f16a, f16b, f8v, f4a, f4b, f2v;       // first-row inserts
    float s16a, s16b, s8v, s4a, s4b, s2v;       // second-row inserts

    // prologue: prefetch for rel = 0
    f16a = bH8[15 * ST8];            f16b = bH8[15 * ST8 + 8 * C_];
    f8v  = bH8[11 * ST8 + 4 * C_];
    f4a  = bH2[9 * ST2];             f4b  = bH2[9 * ST2 + 2 * C_];
    f2v  = bH2[8 * ST2 + C_];
    s16a = bH8[16 * ST8];            s16b = bH8[16 * ST8 + 8 * C_];
    s8v  = bH8[12 * ST8 + 4 * C_];
    s4a  = bH2[10 * ST2];            s4b  = bH2[10 * ST2 + 2 * C_];
    s2v  = bH2[9 * ST2 + C_];

    #pragma unroll
    for (int base = 0; base < CH_; base += 16) {
        #pragma unroll
        for (int p = 0; p < 8; p++) {
            const int u = 2 * p;
            if (base + u >= CH_) break;
            const int rel = base + u;            // compile-time

            // ---- consume prefetched first-row inserts ----
            r16[(u + 15) & 15] = f16a + f16b;
            r8 [(u + 7) & 7]   = f8v;
            r4 [(u + 3) & 3]   = f4a + f4b;
            r2 [(u + 1) & 1]   = f2v;

            // ---- shared cores (excluded slot folded as +0.f) ----
            #define Z16(s) (((s) == (u & 15)) ? 0.f : r16[s])
            const float A16 =
                ((((Z16(0)+Z16(1))+(Z16(2)+Z16(3)))+((Z16(4)+Z16(5))+(Z16(6)+Z16(7))))
               + (((Z16(8)+Z16(9))+(Z16(10)+Z16(11)))+((Z16(12)+Z16(13))+(Z16(14)+Z16(15)))));
            #undef Z16
            #define Z8(s) (((s) == (u & 7)) ? 0.f : r8[s])
            const float A8 = ((Z8(0)+Z8(1))+(Z8(2)+Z8(3)))+((Z8(4)+Z8(5))+(Z8(6)+Z8(7)));
            #undef Z8
            #define Z4(s) (((s) == (u & 3)) ? 0.f : r4[s])
            const float A4 = (Z4(0)+Z4(1))+(Z4(2)+Z4(3));
            #undef Z4

            const float m16_0 = A16 + r16[u & 15];
            const float m8_0  = A8  + r8[u & 7];
            const float m4_0  = A4  + r4[u & 3];
            const float m2_0  = r2[0] + r2[1];

            // ---- consume prefetched second-row inserts ----
            r16[u & 15] = s16a + s16b;
            r8 [u & 7]  = s8v;
            r4 [u & 3]  = s4a + s4b;
            r2 [u & 1]  = s2v;

            const float m16_1 = A16 + r16[u & 15];
            const float m8_1  = A8  + r8[u & 7];
            const float m4_1  = A4  + r4[u & 3];
            const float m2_1  = r2[(u + 1) & 1] + r2[u & 1];

            // ---- issue prefetch for rel+2 (consumed next iteration) ----
            {
                const int rn = rel + 2;          // compile-time; rows stay < RT_
                f16a = bH8[(rn + 15) * ST8];     f16b = bH8[(rn + 15) * ST8 + 8 * C_];
                f8v  = bH8[(rn + 11) * ST8 + 4 * C_];
                f4a  = bH2[(rn + 9) * ST2];      f4b  = bH2[(rn + 9) * ST2 + 2 * C_];
                f2v  = bH2[(rn + 8) * ST2 + C_];
                s16a = bH8[(rn + 16) * ST8];     s16b = bH8[(rn + 16) * ST8 + 8 * C_];
                s8v  = bH8[(rn + 12) * ST8 + 4 * C_];
                s4a  = bH2[(rn + 10) * ST2];     s4b  = bH2[(rn + 10) * ST2 + 2 * C_];
                s2v  = bH2[(rn + 9) * ST2 + C_];
            }

            const float sig0 = tail_sig(m2_0, m4_0, m8_0, m16_0, s_tab[i0 + rel],     tc, s_aw4, c);
            const float sig1 = tail_sig(m2_1, m4_1, m8_1, m16_1, s_tab[i0 + rel + 1], tc, s_aw4, c);
            orr[rel * STX]       = xr[rel * STX]       + sig0;
            orr[(rel + 1) * STX] = xr[(rel + 1) * STX] + sig1;
        }
    }
}

extern "C" void kernel_launch(void* const* d_in, const int* in_sizes, int n_in,
                              void* d_out, int out_size) {
    const float* x    = (const float*)d_in[0];
    const float* olsw = (const float*)d_in[1];
    const float* anch = (const float*)d_in[2];
    const float* wdth = (const float*)d_in[3];
    const float* gmm  = (const float*)d_in[4];
    const float* bta  = (const float*)d_in[5];
    const float* mea  = (const float*)d_in[6];
    const float* vrr  = (const float*)d_in[7];
    float* out = (float*)d_out;

    kA<<<dim3(H_, B_), dim3(C_, 4)>>>(x);
    kB<<<dim3(W_, H_ / CH_, B_), C_>>>(x, olsw, anch, wdth, gmm, bta, mea, vrr, out);
}

// round 17
// speedup vs baseline: 2.2670x; 1.0488x over previous
#include <cuda_runtime.h>
#include <cuda_bf16.h>

#define B_ 4
#define H_ 224
#define W_ 224
#define C_ 64
#define K_ 8
#define EPS_ 1e-6f

#define H2_W 226
#define H8_W 232
#define ST2 (H2_W * C_)
#define ST8 (H8_W * C_)
#define STX (W_ * C_)
#define RT_ 242             // 8 pad + 224 + 10 pad rows (pads stay zero forever)
#define CH_ 56              // rows per kB chunk (4 chunks; 2.02 waves @ 12 blk/SM)

__device__ float g_H2[(size_t)B_ * RT_ * ST2];
__device__ float g_H8[(size_t)B_ * RT_ * ST8];
__device__ float g_rmn[B_ * H_], g_rmx[B_ * H_];

// One-pass streaming front-end: per-row min/max + H2 + H8 (RAW sums).
__global__ void __launch_bounds__(256) kA(const float* __restrict__ x) {
    const int c = threadIdx.x;
    const int seg = threadIdx.y;
    const int t = blockIdx.x;
    const int b = blockIdx.y;

    const float* xr  = x    + (((size_t)b * H_ + t) * W_) * C_ + c;
    float*       h2g = g_H2 + ((size_t)b * RT_ + 8 + t) * ST2 + c;
    float*       h8g = g_H8 + ((size_t)b * RT_ + 8 + t) * ST8 + c;

    const int u0  = seg * 64;
    const int len = (seg == 3) ? (H8_W - 192) : 64;

    float mn = 3.402823466e38f, mx = -3.402823466e38f;
    float ring[8];
    #pragma unroll
    for (int i = 0; i < 8; i++) ring[i] = 0.f;

    float xprev;
    {
        int up = u0 - 8;
        float xp = (up >= 0 && up <= 223) ? xr[up * C_] : 0.f;
        #pragma unroll
        for (int d = -7; d <= -1; d++) {
            const int u = u0 + d;
            float xc = (u >= 0 && u <= 223) ? xr[u * C_] : 0.f;
            ring[(d + 8) & 7] = xp + xc;
            xp = xc;
        }
        xprev = xp;
    }

    for (int base = 0; base < len; base += 8) {
        #pragma unroll
        for (int vv = 0; vv < 8; vv++) {
            const int v = base + vv;
            const int u = u0 + v;
            float xc = 0.f;
            if (u <= 223) {
                xc = xr[u * C_];
                mn = fminf(mn, xc);
                mx = fmaxf(mx, xc);
            }
            const float h2 = xprev + xc;
            xprev = xc;
            ring[v & 7] = h2;
            const float h8 = (h2 + ring[(v - 2) & 7])
                           + (ring[(v - 4) & 7] + ring[(v - 6) & 7]);
            if (u <= 225) h2g[u * C_] = h2;
            h8g[u * C_] = h8;
        }
    }

    #pragma unroll
    for (int o = 16; o; o >>= 1) {
        mn = fminf(mn, __shfl_xor_sync(0xffffffffu, mn, o));
        mx = fmaxf(mx, __shfl_xor_sync(0xffffffffu, mx, o));
    }
    __shared__ float smn[8], smx[8];
    const int tid = threadIdx.y * 64 + threadIdx.x;
    if ((tid & 31) == 0) { smn[tid >> 5] = mn; smx[tid >> 5] = mx; }
    __syncthreads();
    if (tid == 0) {
        #pragma unroll
        for (int i = 1; i < 8; i++) { mn = fminf(mn, smn[i]); mx = fmaxf(mx, smx[i]); }
        g_rmn[b * H_ + t] = mn;
        g_rmx[b * H_ + t] = mx;
    }
}

struct TailC { float inv, c0, c1, c2, c3, bsc, bsh; };  // c0..c3 pre-scaled by ln2

static __device__ __forceinline__ float tail_sig(
    float m2, float m4, float m8, float m16, float4 tb,
    const TailC& tc, const float4* s_aw4, int c)
{
    const float ly0 = __log2f(fmaf(m2,  tc.inv, tb.x));
    const float ly1 = __log2f(fmaf(m4,  tc.inv, tb.y));
    const float ly2 = __log2f(fmaf(m8,  tc.inv, tb.z));
    const float ly3 = __log2f(fmaf(m16, tc.inv, tb.w));
    const float alpha = fmaf(tc.c3, ly3, fmaf(tc.c2, ly2, fmaf(tc.c1, ly1, tc.c0 * ly0)));
    const float a = fmaf(alpha, tc.bsc, tc.bsh);
    float cnt = 0.f;
    #pragma unroll
    for (int k2 = 0; k2 < 4; k2++) {
        const float4 aw = s_aw4[k2 * C_ + c];
        cnt += fmaxf(fmaf(-aw.y, fabsf(a - aw.x), 1.f), 0.f);
        cnt += fmaxf(fmaf(-aw.w, fabsf(a - aw.z), 1.f), 0.f);
    }
    float e, r;
    asm("ex2.approx.ftz.f32 %0, %1;" : "=f"(e) : "f"(cnt * -1.44269504f));
    asm("rcp.approx.ftz.f32 %0, %1;" : "=f"(r) : "f"(1.f + e));
    return r;
}

__global__ void __launch_bounds__(64, 12) kB(
    const float* __restrict__ x,    const float* __restrict__ olsw,
    const float* __restrict__ anch, const float* __restrict__ wdth,
    const float* __restrict__ gmm,  const float* __restrict__ bta,
    const float* __restrict__ mea,  const float* __restrict__ vrr,
    float* __restrict__ out)
{
    const int c = threadIdx.x;
    const int j = blockIdx.x;
    const int i0 = blockIdx.y * CH_;
    const int b = blockIdx.z;

    // Base pointers at relative row 0 == padded row (i0 + 1).
    const float* bH8 = g_H8 + (size_t)b * RT_ * ST8 + (size_t)(i0 + 1) * ST8 + j * C_ + c;
    const float* bH2 = g_H2 + (size_t)b * RT_ * ST2 + (size_t)(i0 + 1) * ST2 + j * C_ + c;
    const float* xr  = x   + ((size_t)b * H_ * W_ + j) * C_ + c + (size_t)i0 * STX;
    float*       orr = out + ((size_t)b * H_ * W_ + j) * C_ + c + (size_t)i0 * STX;

    float r2[2], r4[4], r8[8], r16[16];

    // ==== prefill issued FIRST: latency overlaps reduction + table build ====
    #pragma unroll
    for (int d = -7; d <= 7; d++) {
        const int rr = d + 7;
        r16[rr & 15] = bH8[rr * ST8] + bH8[rr * ST8 + 8 * C_];
        if (d >= -3 && d <= 3) r8[d + 3] = bH8[rr * ST8 + 4 * C_];
        if (d >= -1 && d <= 1) r4[d + 1] = bH2[rr * ST2] + bH2[rr * ST2 + 2 * C_];
        if (d == 0)            r2[0]     = bH2[rr * ST2 + C_];
    }

    // pipeline prefetch registers (next iteration's 12 loads)
    float f16a, f16b, f8v, f4a, f4b, f2v;
    float s16a, s16b, s8v, s4a, s4b, s2v;
    f16a = bH8[15 * ST8];            f16b = bH8[15 * ST8 + 8 * C_];
    f8v  = bH8[11 * ST8 + 4 * C_];
    f4a  = bH2[9 * ST2];             f4b  = bH2[9 * ST2 + 2 * C_];
    f2v  = bH2[8 * ST2 + C_];
    s16a = bH8[16 * ST8];            s16b = bH8[16 * ST8 + 8 * C_];
    s8v  = bH8[12 * ST8 + 4 * C_];
    s4a  = bH2[10 * ST2];            s4b  = bH2[10 * ST2 + 2 * C_];
    s2v  = bH2[9 * ST2 + C_];

    // ==== per-sample min/max ====
    float mn = 3.402823466e38f, mx = -3.402823466e38f;
    for (int i = c; i < H_; i += 64) {
        mn = fminf(mn, g_rmn[b * H_ + i]);
        mx = fmaxf(mx, g_rmx[b * H_ + i]);
    }
    #pragma unroll
    for (int o = 16; o; o >>= 1) {
        mn = fminf(mn, __shfl_xor_sync(0xffffffffu, mn, o));
        mx = fmaxf(mx, __shfl_xor_sync(0xffffffffu, mx, o));
    }
    __shared__ float sred[4];
    if ((c & 31) == 0) { sred[(c >> 5)] = mn; sred[(c >> 5) + 2] = mx; }
    __syncthreads();
    mn = fminf(sred[0], sred[1]);
    mx = fmaxf(sred[2], sred[3]);

    const float w0 = olsw[0], w1 = olsw[1], w2 = olsw[2], w3 = olsw[3];
    const float L1 = 0.69314718f, L2 = 1.38629436f, L3 = 2.07944154f, L4 = 2.77258872f;
    const float wsum = w0 + w1 + w2 + w3;
    const float lrb = (w0 * L1 + w1 * L2 + w2 * L3 + w3 * L4) / wsum;
    const float d0 = L1 - lrb, d1 = L2 - lrb, d2 = L3 - lrb, d3 = L4 - lrb;
    const float den = w0 * d0 * d0 + w1 * d1 * d1 + w2 * d2 * d2 + w3 * d3 * d3;
    const float ivd = (1.f / den) * 0.69314718056f;   // fold ln2 (log2 -> ln)

    TailC tc;
    tc.inv = 1.f / (mx - mn + EPS_);
    tc.c0 = w0 * d0 * ivd; tc.c1 = w1 * d1 * ivd;
    tc.c2 = w2 * d2 * ivd; tc.c3 = w3 * d3 * ivd;
    tc.bsc = gmm[c] * rsqrtf(vrr[c] + 1e-3f);
    tc.bsh = bta[c] - mea[c] * tc.bsc;

    __shared__ float4 s_aw4[4 * C_];
    #pragma unroll
    for (int k2 = 0; k2 < 4; k2++)
        s_aw4[k2 * C_ + c] = make_float4(anch[c * K_ + 2 * k2],     wdth[c * K_ + 2 * k2],
                                         anch[c * K_ + 2 * k2 + 1], wdth[c * K_ + 2 * k2 + 1]);

    const float mi  = mn * tc.inv;
    const float nc2  = (float)(min(j + 1, 223) - j + 1);
    const float nc4  = (float)(min(j + 2, 223) - max(j - 1, 0) + 1);
    const float nc8  = (float)(min(j + 4, 223) - max(j - 3, 0) + 1);
    const float nc16 = (float)(min(j + 8, 223) - max(j - 7, 0) + 1);

    __shared__ float4 s_tab[H_];
    for (int i = c; i < H_; i += 64) {
        float nr2  = (float)(min(i + 1, 223) - i + 1);
        float nr4  = (float)(min(i + 2, 223) - max(i - 1, 0) + 1);
        float nr8  = (float)(min(i + 4, 223) - max(i - 3, 0) + 1);
        float nr16 = (float)(min(i + 8, 223) - max(i - 7, 0) + 1);
        s_tab[i] = make_float4(EPS_ - nr2 * nc2 * mi,  EPS_ - nr4 * nc4 * mi,
                               EPS_ - nr8 * nc8 * mi,  EPS_ - nr16 * nc16 * mi);
    }
    __syncthreads();

    #pragma unroll
    for (int base = 0; base < CH_; base += 16) {
        #pragma unroll
        for (int p = 0; p < 8; p++) {
            const int u = 2 * p;
            if (base + u >= CH_) break;
            const int rel = base + u;            // compile-time

            // ---- consume prefetched first-row inserts ----
            r16[(u + 15) & 15] = f16a + f16b;
            r8 [(u + 7) & 7]   = f8v;
            r4 [(u + 3) & 3]   = f4a + f4b;
            r2 [(u + 1) & 1]   = f2v;

            // ---- shared cores (excluded slot folded as +0.f) ----
            #define Z16(s) (((s) == (u & 15)) ? 0.f : r16[s])
            const float A16 =
                ((((Z16(0)+Z16(1))+(Z16(2)+Z16(3)))+((Z16(4)+Z16(5))+(Z16(6)+Z16(7))))
               + (((Z16(8)+Z16(9))+(Z16(10)+Z16(11)))+((Z16(12)+Z16(13))+(Z16(14)+Z16(15)))));
            #undef Z16
            #define Z8(s) (((s) == (u & 7)) ? 0.f : r8[s])
            const float A8 = ((Z8(0)+Z8(1))+(Z8(2)+Z8(3)))+((Z8(4)+Z8(5))+(Z8(6)+Z8(7)));
            #undef Z8
            #define Z4(s) (((s) == (u & 3)) ? 0.f : r4[s])
            const float A4 = (Z4(0)+Z4(1))+(Z4(2)+Z4(3));
            #undef Z4

            const float m16_0 = A16 + r16[u & 15];
            const float m8_0  = A8  + r8[u & 7];
            const float m4_0  = A4  + r4[u & 3];
            const float m2_0  = r2[0] + r2[1];

            // ---- consume prefetched second-row inserts ----
            r16[u & 15] = s16a + s16b;
            r8 [u & 7]  = s8v;
            r4 [u & 3]  = s4a + s4b;
            r2 [u & 1]  = s2v;

            const float m16_1 = A16 + r16[u & 15];
            const float m8_1  = A8  + r8[u & 7];
            const float m4_1  = A4  + r4[u & 3];
            const float m2_1  = r2[(u + 1) & 1] + r2[u & 1];

            // ---- issue prefetch for rel+2 (consumed next iteration) ----
            {
                const int rn = rel + 2;          // compile-time; rows stay < RT_
                f16a = bH8[(rn + 15) * ST8];     f16b = bH8[(rn + 15) * ST8 + 8 * C_];
                f8v  = bH8[(rn + 11) * ST8 + 4 * C_];
                f4a  = bH2[(rn + 9) * ST2];      f4b  = bH2[(rn + 9) * ST2 + 2 * C_];
                f2v  = bH2[(rn + 8) * ST2 + C_];
                s16a = bH8[(rn + 16) * ST8];     s16b = bH8[(rn + 16) * ST8 + 8 * C_];
                s8v  = bH8[(rn + 12) * ST8 + 4 * C_];
                s4a  = bH2[(rn + 10) * ST2];     s4b  = bH2[(rn + 10) * ST2 + 2 * C_];
                s2v  = bH2[(rn + 9) * ST2 + C_];
            }

            const float sig0 = tail_sig(m2_0, m4_0, m8_0, m16_0, s_tab[i0 + rel],     tc, s_aw4, c);
            const float sig1 = tail_sig(m2_1, m4_1, m8_1, m16_1, s_tab[i0 + rel + 1], tc, s_aw4, c);
            orr[rel * STX]       = xr[rel * STX]       + sig0;
            orr[(rel + 1) * STX] = xr[(rel + 1) * STX] + sig1;
        }
    }
}

extern "C" void kernel_launch(void* const* d_in, const int* in_sizes, int n_in,
                              void* d_out, int out_size) {
    const float* x    = (const float*)d_in[0];
    const float* olsw = (const float*)d_in[1];
    const float* anch = (const float*)d_in[2];
    const float* wdth = (const float*)d_in[3];
    const float* gmm  = (const float*)d_in[4];
    const float* bta  = (const float*)d_in[5];
    const float* mea  = (const float*)d_in[6];
    const float* vrr  = (const float*)d_in[7];
    float* out = (float*)d_out;

    kA<<<dim3(H_, B_), dim3(C_, 4)>>>(x);
    kB<<<dim3(W_, H_ / CH_, B_), C_>>>(x, olsw, anch, wdth, gmm, bta, mea, vrr, out);
}